// round 13
// baseline (speedup 1.0000x reference)
#include <cuda_runtime.h>

// Problem constants
#define Bn 32    // batch
#define Np 576   // patches
#define Wc 32    // concepts per sample
#define Dd 256   // embed dim

// Scratch (allocation-free rule: __device__ globals)
__device__ float g_img[Bn * Np * Dd];   // normalized image tokens
__device__ float g_con[Bn * Wc * Dd];   // normalized concept vectors
__device__ float g_max[Bn * Bn * Wc];   // max over patches, [m][c][w]

// ---------------------------------------------------------------------------
// Kernel 1: L2-normalize rows of D=256 (matches F.normalize: x / max(||x||,eps))
// one block (64 threads) per row; each thread owns one float4
// ---------------------------------------------------------------------------
__global__ void norm_kernel(const float* __restrict__ src, int which) {
    const int row = blockIdx.x;
    const int t = threadIdx.x;  // 0..63
    const float4* s = (const float4*)(src + (long)row * Dd);
    float4 v = s[t];
    float ss = v.x * v.x + v.y * v.y + v.z * v.z + v.w * v.w;
#pragma unroll
    for (int o = 16; o > 0; o >>= 1) ss += __shfl_xor_sync(0xffffffffu, ss, o);
    __shared__ float sh[2];
    if ((t & 31) == 0) sh[t >> 5] = ss;
    __syncthreads();
    const float tot = sh[0] + sh[1];
    const float inv = 1.0f / fmaxf(sqrtf(tot), 1e-12f);
    v.x *= inv; v.y *= inv; v.z *= inv; v.w *= inv;
    float* dst = which ? g_con : g_img;
    ((float4*)(dst + (long)row * Dd))[t] = v;
}

// ---------------------------------------------------------------------------
// Kernel 2: per (m,c) block — 576x32x256 GEMM fused with max over the 576 rows
// 128 threads, each computes a 4x4 register tile of a 64x32 output tile.
// Smem is k-transposed with XOR swizzle -> conflict-free fills and loads.
// ---------------------------------------------------------------------------
#define RS 68  // img_s row stride (floats), row index = local k
#define CS 36  // con_t row stride (floats), row index = global k

__global__ __launch_bounds__(128, 4) void main_kernel() {
    __shared__ __align__(16) float con_t[Dd][CS];  // [k][w ^ (k&28)]        36864 B
    __shared__ __align__(16) float img_s[32][RS];  // [k local][n ^ (k&28)]   8704 B
    __shared__ float red[16][32];                  //                         2048 B

    const int m = blockIdx.x;
    const int c = blockIdx.y;
    const int t = threadIdx.x;
    const int tyr = t >> 3;  // 0..15 : row group (rows 4*tyr .. 4*tyr+3)
    const int txw = t & 7;   // 0..7  : col group (cols 4*txw .. 4*txw+3)
    const float* __restrict__ conp = g_con + (long)c * Wc * Dd;
    const float* __restrict__ imgp = g_img + (long)m * Np * Dd;

    // Fill con_t (whole 32x256 concept matrix, k-transposed, swizzled).
    // Coalesced global reads: 32 lanes x float4 along k.
    for (int idx = t; idx < Wc * (Dd / 4); idx += 128) {
        const int w = idx >> 6;            // 0..31
        const int k4 = (idx & 63) << 2;    // 0..252, multiple of 4
        const float4 v = *(const float4*)(conp + w * Dd + k4);
        const int sw = k4 & 28;            // same swizzle for k4..k4+3
        con_t[k4 + 0][w ^ sw] = v.x;
        con_t[k4 + 1][w ^ sw] = v.y;
        con_t[k4 + 2][w ^ sw] = v.z;
        con_t[k4 + 3][w ^ sw] = v.w;
    }

    float mx0 = -1e30f, mx1 = -1e30f, mx2 = -1e30f, mx3 = -1e30f;

    for (int n0 = 0; n0 < Np; n0 += 64) {
        float acc[4][4];
#pragma unroll
        for (int i = 0; i < 4; i++)
#pragma unroll
            for (int j = 0; j < 4; j++) acc[i][j] = 0.0f;

        for (int kt = 0; kt < Dd; kt += 32) {
            __syncthreads();  // img_s consumed by previous tile / con_t ready
            // Load 64(n) x 32(k) img tile, k-transposed + swizzled.
            // Global: 4 rows x 128B per warp -> fully coalesced.
#pragma unroll
            for (int p = 0; p < 4; p++) {
                const int idx = t + p * 128;      // 0..511
                const int n = idx >> 3;           // 0..63
                const int k4 = (idx & 7) << 2;    // 0..28
                const float4 v = *(const float4*)(imgp + (n0 + n) * Dd + kt + k4);
                img_s[k4 + 0][n ^ k4] = v.x;
                img_s[k4 + 1][n ^ k4] = v.y;
                img_s[k4 + 2][n ^ k4] = v.z;
                img_s[k4 + 3][n ^ k4] = v.w;
            }
            __syncthreads();

#pragma unroll
            for (int k = 0; k < 32; k++) {
                const int ks = k & 28;  // (kt+k)&28 == k&28 since kt % 32 == 0
                const float4 a = *(const float4*)&img_s[k][(tyr << 2) ^ ks];
                const float4 b = *(const float4*)&con_t[kt + k][(txw << 2) ^ ks];
                acc[0][0] = fmaf(a.x, b.x, acc[0][0]);
                acc[0][1] = fmaf(a.x, b.y, acc[0][1]);
                acc[0][2] = fmaf(a.x, b.z, acc[0][2]);
                acc[0][3] = fmaf(a.x, b.w, acc[0][3]);
                acc[1][0] = fmaf(a.y, b.x, acc[1][0]);
                acc[1][1] = fmaf(a.y, b.y, acc[1][1]);
                acc[1][2] = fmaf(a.y, b.z, acc[1][2]);
                acc[1][3] = fmaf(a.y, b.w, acc[1][3]);
                acc[2][0] = fmaf(a.z, b.x, acc[2][0]);
                acc[2][1] = fmaf(a.z, b.y, acc[2][1]);
                acc[2][2] = fmaf(a.z, b.z, acc[2][2]);
                acc[2][3] = fmaf(a.z, b.w, acc[2][3]);
                acc[3][0] = fmaf(a.w, b.x, acc[3][0]);
                acc[3][1] = fmaf(a.w, b.y, acc[3][1]);
                acc[3][2] = fmaf(a.w, b.z, acc[3][2]);
                acc[3][3] = fmaf(a.w, b.w, acc[3][3]);
            }
        }
        // fold this n-tile into the per-column running max
#pragma unroll
        for (int i = 0; i < 4; i++) {
            mx0 = fmaxf(mx0, acc[i][0]);
            mx1 = fmaxf(mx1, acc[i][1]);
            mx2 = fmaxf(mx2, acc[i][2]);
            mx3 = fmaxf(mx3, acc[i][3]);
        }
    }

    __syncthreads();
    red[tyr][(txw << 2) + 0] = mx0;
    red[tyr][(txw << 2) + 1] = mx1;
    red[tyr][(txw << 2) + 2] = mx2;
    red[tyr][(txw << 2) + 3] = mx3;
    __syncthreads();
    if (t < 32) {
        float v = red[0][t];
#pragma unroll
        for (int i = 1; i < 16; i++) v = fmaxf(v, red[i][t]);
        g_max[((long)(m * Bn + c)) * Wc + t] = v;
    }
}

// ---------------------------------------------------------------------------
// Kernel 3: masked mean over valid concepts, logits, log-sigmoid, final mean
// ---------------------------------------------------------------------------
__global__ void finish_kernel(const int* __restrict__ lens,
                              const float* __restrict__ scale,
                              const float* __restrict__ bias,
                              float* __restrict__ out) {
    const int t = threadIdx.x;  // 0..1023
    const int m = t >> 5;
    const int c = t & 31;
    const int L = lens[c];
    const float* row = g_max + ((long)(m * Bn + c)) * Wc;
    float s = 0.0f;
#pragma unroll
    for (int w = 0; w < Wc; w++)
        if (w < L) s += row[w];
    const float sim = s / (float)L;
    const float ls = fminf(fmaxf(scale[0], -10.0f), 10.0f);
    const float tsc = expf(ls);
    const float logit = fminf(fmaxf(tsc * sim + bias[0], -50.0f), 50.0f);
    const float zl = (m == c) ? logit : -logit;
    // stable log_sigmoid(zl) = min(zl,0) - log1p(exp(-|zl|))
    const float lsig = fminf(zl, 0.0f) - log1pf(expf(-fabsf(zl)));
    float v = -lsig;

#pragma unroll
    for (int o = 16; o > 0; o >>= 1) v += __shfl_xor_sync(0xffffffffu, v, o);
    __shared__ float sh[32];
    if ((t & 31) == 0) sh[t >> 5] = v;
    __syncthreads();
    if (t < 32) {
        float x = sh[t];
#pragma unroll
        for (int o = 16; o > 0; o >>= 1) x += __shfl_xor_sync(0xffffffffu, x, o);
        if (t == 0) out[0] = x * (1.0f / (Bn * Bn));
    }
}

// ---------------------------------------------------------------------------
// Launch: identify inputs by element count (robust to metadata ordering;
// the two size-1 scalars appear scale-before-bias in both orderings).
// All launches on the capture stream; graph-capturable (no syncs/allocs).
// ---------------------------------------------------------------------------
extern "C" void kernel_launch(void* const* d_in, const int* in_sizes, int n_in,
                              void* d_out, int out_size) {
    const float* img = nullptr;
    const float* con = nullptr;
    const int* lens = nullptr;
    const float* scale = nullptr;
    const float* bias = nullptr;
    for (int i = 0; i < n_in; i++) {
        const long s = in_sizes[i];
        if (s == (long)Bn * Np * Dd) img = (const float*)d_in[i];
        else if (s == (long)Bn * Wc * Dd) con = (const float*)d_in[i];
        else if (s == Bn) lens = (const int*)d_in[i];
        else if (s == 1) { if (!scale) scale = (const float*)d_in[i]; else bias = (const float*)d_in[i]; }
    }

    norm_kernel<<<Bn * Np, 64>>>(img, 0);
    norm_kernel<<<Bn * Wc, 64>>>(con, 1);
    dim3 grid(Bn, Bn);
    main_kernel<<<grid, 128>>>();
    finish_kernel<<<1, 1024>>>(lens, scale, bias, (float*)d_out);
}

// round 14
// speedup vs baseline: 1.0028x; 1.0028x over previous
#include <cuda_runtime.h>

// Problem constants
#define Bn 32    // batch
#define Np 576   // patches
#define Wc 32    // concepts per sample
#define Dd 256   // embed dim

// Scratch (allocation-free rule: __device__ globals)
__device__ float g_img[Bn * Np * Dd];   // normalized image tokens
__device__ float g_con[Bn * Wc * Dd];   // normalized concept vectors
__device__ float g_max[Bn * Bn * Wc];   // max over patches, [m][c][w]

// ---------------------------------------------------------------------------
// Kernel 1: L2-normalize rows of D=256 (matches F.normalize: x / max(||x||,eps))
// one block (64 threads) per row; each thread owns one float4
// ---------------------------------------------------------------------------
__global__ void norm_kernel(const float* __restrict__ src, int which) {
    const int row = blockIdx.x;
    const int t = threadIdx.x;  // 0..63
    const float4* s = (const float4*)(src + (long)row * Dd);
    float4 v = s[t];
    float ss = v.x * v.x + v.y * v.y + v.z * v.z + v.w * v.w;
#pragma unroll
    for (int o = 16; o > 0; o >>= 1) ss += __shfl_xor_sync(0xffffffffu, ss, o);
    __shared__ float sh[2];
    if ((t & 31) == 0) sh[t >> 5] = ss;
    __syncthreads();
    const float tot = sh[0] + sh[1];
    const float inv = 1.0f / fmaxf(sqrtf(tot), 1e-12f);
    v.x *= inv; v.y *= inv; v.z *= inv; v.w *= inv;
    float* dst = which ? g_con : g_img;
    ((float4*)(dst + (long)row * Dd))[t] = v;
}

// ---------------------------------------------------------------------------
// Kernel 2: per (m,c) block — 576x32x256 GEMM fused with max over the 576 rows
// 128 threads, each computes a 4x4 register tile of a 64x32 output tile.
// Smem is k-transposed with XOR swizzle -> conflict-free fills and loads.
// ---------------------------------------------------------------------------
#define RS 68  // img_s row stride (floats), row index = local k
#define CS 36  // con_t row stride (floats), row index = global k

__global__ __launch_bounds__(128, 4) void main_kernel() {
    __shared__ __align__(16) float con_t[Dd][CS];  // [k][w ^ (k&28)]        36864 B
    __shared__ __align__(16) float img_s[32][RS];  // [k local][n ^ (k&28)]   8704 B
    __shared__ float red[16][32];                  //                         2048 B

    const int m = blockIdx.x;
    const int c = blockIdx.y;
    const int t = threadIdx.x;
    const int tyr = t >> 3;  // 0..15 : row group (rows 4*tyr .. 4*tyr+3)
    const int txw = t & 7;   // 0..7  : col group (cols 4*txw .. 4*txw+3)
    const float* __restrict__ conp = g_con + (long)c * Wc * Dd;
    const float* __restrict__ imgp = g_img + (long)m * Np * Dd;

    // Fill con_t (whole 32x256 concept matrix, k-transposed, swizzled).
    // Coalesced global reads: 32 lanes x float4 along k.
    for (int idx = t; idx < Wc * (Dd / 4); idx += 128) {
        const int w = idx >> 6;            // 0..31
        const int k4 = (idx & 63) << 2;    // 0..252, multiple of 4
        const float4 v = *(const float4*)(conp + w * Dd + k4);
        const int sw = k4 & 28;            // same swizzle for k4..k4+3
        con_t[k4 + 0][w ^ sw] = v.x;
        con_t[k4 + 1][w ^ sw] = v.y;
        con_t[k4 + 2][w ^ sw] = v.z;
        con_t[k4 + 3][w ^ sw] = v.w;
    }

    float mx0 = -1e30f, mx1 = -1e30f, mx2 = -1e30f, mx3 = -1e30f;

    for (int n0 = 0; n0 < Np; n0 += 64) {
        float acc[4][4];
#pragma unroll
        for (int i = 0; i < 4; i++)
#pragma unroll
            for (int j = 0; j < 4; j++) acc[i][j] = 0.0f;

        for (int kt = 0; kt < Dd; kt += 32) {
            __syncthreads();  // img_s consumed by previous tile / con_t ready
            // Load 64(n) x 32(k) img tile, k-transposed + swizzled.
            // Global: 4 rows x 128B per warp -> fully coalesced.
#pragma unroll
            for (int p = 0; p < 4; p++) {
                const int idx = t + p * 128;      // 0..511
                const int n = idx >> 3;           // 0..63
                const int k4 = (idx & 7) << 2;    // 0..28
                const float4 v = *(const float4*)(imgp + (n0 + n) * Dd + kt + k4);
                img_s[k4 + 0][n ^ k4] = v.x;
                img_s[k4 + 1][n ^ k4] = v.y;
                img_s[k4 + 2][n ^ k4] = v.z;
                img_s[k4 + 3][n ^ k4] = v.w;
            }
            __syncthreads();

#pragma unroll
            for (int k = 0; k < 32; k++) {
                const int ks = k & 28;  // (kt+k)&28 == k&28 since kt % 32 == 0
                const float4 a = *(const float4*)&img_s[k][(tyr << 2) ^ ks];
                const float4 b = *(const float4*)&con_t[kt + k][(txw << 2) ^ ks];
                acc[0][0] = fmaf(a.x, b.x, acc[0][0]);
                acc[0][1] = fmaf(a.x, b.y, acc[0][1]);
                acc[0][2] = fmaf(a.x, b.z, acc[0][2]);
                acc[0][3] = fmaf(a.x, b.w, acc[0][3]);
                acc[1][0] = fmaf(a.y, b.x, acc[1][0]);
                acc[1][1] = fmaf(a.y, b.y, acc[1][1]);
                acc[1][2] = fmaf(a.y, b.z, acc[1][2]);
                acc[1][3] = fmaf(a.y, b.w, acc[1][3]);
                acc[2][0] = fmaf(a.z, b.x, acc[2][0]);
                acc[2][1] = fmaf(a.z, b.y, acc[2][1]);
                acc[2][2] = fmaf(a.z, b.z, acc[2][2]);
                acc[2][3] = fmaf(a.z, b.w, acc[2][3]);
                acc[3][0] = fmaf(a.w, b.x, acc[3][0]);
                acc[3][1] = fmaf(a.w, b.y, acc[3][1]);
                acc[3][2] = fmaf(a.w, b.z, acc[3][2]);
                acc[3][3] = fmaf(a.w, b.w, acc[3][3]);
            }
        }
        // fold this n-tile into the per-column running max
#pragma unroll
        for (int i = 0; i < 4; i++) {
            mx0 = fmaxf(mx0, acc[i][0]);
            mx1 = fmaxf(mx1, acc[i][1]);
            mx2 = fmaxf(mx2, acc[i][2]);
            mx3 = fmaxf(mx3, acc[i][3]);
        }
    }

    __syncthreads();
    red[tyr][(txw << 2) + 0] = mx0;
    red[tyr][(txw << 2) + 1] = mx1;
    red[tyr][(txw << 2) + 2] = mx2;
    red[tyr][(txw << 2) + 3] = mx3;
    __syncthreads();
    if (t < 32) {
        float v = red[0][t];
#pragma unroll
        for (int i = 1; i < 16; i++) v = fmaxf(v, red[i][t]);
        g_max[((long)(m * Bn + c)) * Wc + t] = v;
    }
}

// ---------------------------------------------------------------------------
// Kernel 3: masked mean over valid concepts, logits, log-sigmoid, final mean
// ---------------------------------------------------------------------------
__global__ void finish_kernel(const int* __restrict__ lens,
                              const float* __restrict__ scale,
                              const float* __restrict__ bias,
                              float* __restrict__ out) {
    const int t = threadIdx.x;  // 0..1023
    const int m = t >> 5;
    const int c = t & 31;
    const int L = lens[c];
    const float* row = g_max + ((long)(m * Bn + c)) * Wc;
    float s = 0.0f;
#pragma unroll
    for (int w = 0; w < Wc; w++)
        if (w < L) s += row[w];
    const float sim = s / (float)L;
    const float ls = fminf(fmaxf(scale[0], -10.0f), 10.0f);
    const float tsc = expf(ls);
    const float logit = fminf(fmaxf(tsc * sim + bias[0], -50.0f), 50.0f);
    const float zl = (m == c) ? logit : -logit;
    // stable log_sigmoid(zl) = min(zl,0) - log1p(exp(-|zl|))
    const float lsig = fminf(zl, 0.0f) - log1pf(expf(-fabsf(zl)));
    float v = -lsig;

#pragma unroll
    for (int o = 16; o > 0; o >>= 1) v += __shfl_xor_sync(0xffffffffu, v, o);
    __shared__ float sh[32];
    if ((t & 31) == 0) sh[t >> 5] = v;
    __syncthreads();
    if (t < 32) {
        float x = sh[t];
#pragma unroll
        for (int o = 16; o > 0; o >>= 1) x += __shfl_xor_sync(0xffffffffu, x, o);
        if (t == 0) out[0] = x * (1.0f / (Bn * Bn));
    }
}

// ---------------------------------------------------------------------------
// Launch: identify inputs by element count (robust to metadata ordering;
// the two size-1 scalars appear scale-before-bias in both orderings).
// All launches on the capture stream; graph-capturable (no syncs/allocs).
// ---------------------------------------------------------------------------
extern "C" void kernel_launch(void* const* d_in, const int* in_sizes, int n_in,
                              void* d_out, int out_size) {
    const float* img = nullptr;
    const float* con = nullptr;
    const int* lens = nullptr;
    const float* scale = nullptr;
    const float* bias = nullptr;
    for (int i = 0; i < n_in; i++) {
        const long s = in_sizes[i];
        if (s == (long)Bn * Np * Dd) img = (const float*)d_in[i];
        else if (s == (long)Bn * Wc * Dd) con = (const float*)d_in[i];
        else if (s == Bn) lens = (const int*)d_in[i];
        else if (s == 1) { if (!scale) scale = (const float*)d_in[i]; else bias = (const float*)d_in[i]; }
    }

    norm_kernel<<<Bn * Np, 64>>>(img, 0);
    norm_kernel<<<Bn * Wc, 64>>>(con, 1);
    dim3 grid(Bn, Bn);
    main_kernel<<<grid, 128>>>();
    finish_kernel<<<1, 1024>>>(lens, scale, bias, (float*)d_out);
}

// round 15
// speedup vs baseline: 1.0033x; 1.0005x over previous
#include <cuda_runtime.h>

// Problem constants
#define Bn 32    // batch
#define Np 576   // patches
#define Wc 32    // concepts per sample
#define Dd 256   // embed dim

// Scratch (allocation-free rule: __device__ globals)
__device__ float g_img[Bn * Np * Dd];   // normalized image tokens
__device__ float g_con[Bn * Wc * Dd];   // normalized concept vectors
__device__ float g_max[Bn * Bn * Wc];   // max over patches, [m][c][w]

// ---------------------------------------------------------------------------
// Kernel 1: L2-normalize rows of D=256 (matches F.normalize: x / max(||x||,eps))
// one block (64 threads) per row; each thread owns one float4
// ---------------------------------------------------------------------------
__global__ void norm_kernel(const float* __restrict__ src, int which) {
    const int row = blockIdx.x;
    const int t = threadIdx.x;  // 0..63
    const float4* s = (const float4*)(src + (long)row * Dd);
    float4 v = s[t];
    float ss = v.x * v.x + v.y * v.y + v.z * v.z + v.w * v.w;
#pragma unroll
    for (int o = 16; o > 0; o >>= 1) ss += __shfl_xor_sync(0xffffffffu, ss, o);
    __shared__ float sh[2];
    if ((t & 31) == 0) sh[t >> 5] = ss;
    __syncthreads();
    const float tot = sh[0] + sh[1];
    const float inv = 1.0f / fmaxf(sqrtf(tot), 1e-12f);
    v.x *= inv; v.y *= inv; v.z *= inv; v.w *= inv;
    float* dst = which ? g_con : g_img;
    ((float4*)(dst + (long)row * Dd))[t] = v;
}

// ---------------------------------------------------------------------------
// Kernel 2: per (m,c) block — 576x32x256 GEMM fused with max over the 576 rows
// 128 threads, each computes a 4x4 register tile of a 64x32 output tile.
// Smem is k-transposed with XOR swizzle -> conflict-free fills and loads.
// ---------------------------------------------------------------------------
#define RS 68  // img_s row stride (floats), row index = local k
#define CS 36  // con_t row stride (floats), row index = global k

__global__ __launch_bounds__(128, 4) void main_kernel() {
    __shared__ __align__(16) float con_t[Dd][CS];  // [k][w ^ (k&28)]        36864 B
    __shared__ __align__(16) float img_s[32][RS];  // [k local][n ^ (k&28)]   8704 B
    __shared__ float red[16][32];                  //                         2048 B

    const int m = blockIdx.x;
    const int c = blockIdx.y;
    const int t = threadIdx.x;
    const int tyr = t >> 3;  // 0..15 : row group (rows 4*tyr .. 4*tyr+3)
    const int txw = t & 7;   // 0..7  : col group (cols 4*txw .. 4*txw+3)
    const float* __restrict__ conp = g_con + (long)c * Wc * Dd;
    const float* __restrict__ imgp = g_img + (long)m * Np * Dd;

    // Fill con_t (whole 32x256 concept matrix, k-transposed, swizzled).
    // Coalesced global reads: 32 lanes x float4 along k.
    for (int idx = t; idx < Wc * (Dd / 4); idx += 128) {
        const int w = idx >> 6;            // 0..31
        const int k4 = (idx & 63) << 2;    // 0..252, multiple of 4
        const float4 v = *(const float4*)(conp + w * Dd + k4);
        const int sw = k4 & 28;            // same swizzle for k4..k4+3
        con_t[k4 + 0][w ^ sw] = v.x;
        con_t[k4 + 1][w ^ sw] = v.y;
        con_t[k4 + 2][w ^ sw] = v.z;
        con_t[k4 + 3][w ^ sw] = v.w;
    }

    float mx0 = -1e30f, mx1 = -1e30f, mx2 = -1e30f, mx3 = -1e30f;

    for (int n0 = 0; n0 < Np; n0 += 64) {
        float acc[4][4];
#pragma unroll
        for (int i = 0; i < 4; i++)
#pragma unroll
            for (int j = 0; j < 4; j++) acc[i][j] = 0.0f;

        for (int kt = 0; kt < Dd; kt += 32) {
            __syncthreads();  // img_s consumed by previous tile / con_t ready
            // Load 64(n) x 32(k) img tile, k-transposed + swizzled.
            // Global: 4 rows x 128B per warp -> fully coalesced.
#pragma unroll
            for (int p = 0; p < 4; p++) {
                const int idx = t + p * 128;      // 0..511
                const int n = idx >> 3;           // 0..63
                const int k4 = (idx & 7) << 2;    // 0..28
                const float4 v = *(const float4*)(imgp + (n0 + n) * Dd + kt + k4);
                img_s[k4 + 0][n ^ k4] = v.x;
                img_s[k4 + 1][n ^ k4] = v.y;
                img_s[k4 + 2][n ^ k4] = v.z;
                img_s[k4 + 3][n ^ k4] = v.w;
            }
            __syncthreads();

#pragma unroll
            for (int k = 0; k < 32; k++) {
                const int ks = k & 28;  // (kt+k)&28 == k&28 since kt % 32 == 0
                const float4 a = *(const float4*)&img_s[k][(tyr << 2) ^ ks];
                const float4 b = *(const float4*)&con_t[kt + k][(txw << 2) ^ ks];
                acc[0][0] = fmaf(a.x, b.x, acc[0][0]);
                acc[0][1] = fmaf(a.x, b.y, acc[0][1]);
                acc[0][2] = fmaf(a.x, b.z, acc[0][2]);
                acc[0][3] = fmaf(a.x, b.w, acc[0][3]);
                acc[1][0] = fmaf(a.y, b.x, acc[1][0]);
                acc[1][1] = fmaf(a.y, b.y, acc[1][1]);
                acc[1][2] = fmaf(a.y, b.z, acc[1][2]);
                acc[1][3] = fmaf(a.y, b.w, acc[1][3]);
                acc[2][0] = fmaf(a.z, b.x, acc[2][0]);
                acc[2][1] = fmaf(a.z, b.y, acc[2][1]);
                acc[2][2] = fmaf(a.z, b.z, acc[2][2]);
                acc[2][3] = fmaf(a.z, b.w, acc[2][3]);
                acc[3][0] = fmaf(a.w, b.x, acc[3][0]);
                acc[3][1] = fmaf(a.w, b.y, acc[3][1]);
                acc[3][2] = fmaf(a.w, b.z, acc[3][2]);
                acc[3][3] = fmaf(a.w, b.w, acc[3][3]);
            }
        }
        // fold this n-tile into the per-column running max
#pragma unroll
        for (int i = 0; i < 4; i++) {
            mx0 = fmaxf(mx0, acc[i][0]);
            mx1 = fmaxf(mx1, acc[i][1]);
            mx2 = fmaxf(mx2, acc[i][2]);
            mx3 = fmaxf(mx3, acc[i][3]);
        }
    }

    __syncthreads();
    red[tyr][(txw << 2) + 0] = mx0;
    red[tyr][(txw << 2) + 1] = mx1;
    red[tyr][(txw << 2) + 2] = mx2;
    red[tyr][(txw << 2) + 3] = mx3;
    __syncthreads();
    if (t < 32) {
        float v = red[0][t];
#pragma unroll
        for (int i = 1; i < 16; i++) v = fmaxf(v, red[i][t]);
        g_max[((long)(m * Bn + c)) * Wc + t] = v;
    }
}

// ---------------------------------------------------------------------------
// Kernel 3: masked mean over valid concepts, logits, log-sigmoid, final mean
// ---------------------------------------------------------------------------
__global__ void finish_kernel(const int* __restrict__ lens,
                              const float* __restrict__ scale,
                              const float* __restrict__ bias,
                              float* __restrict__ out) {
    const int t = threadIdx.x;  // 0..1023
    const int m = t >> 5;
    const int c = t & 31;
    const int L = lens[c];
    const float* row = g_max + ((long)(m * Bn + c)) * Wc;
    float s = 0.0f;
#pragma unroll
    for (int w = 0; w < Wc; w++)
        if (w < L) s += row[w];
    const float sim = s / (float)L;
    const float ls = fminf(fmaxf(scale[0], -10.0f), 10.0f);
    const float tsc = expf(ls);
    const float logit = fminf(fmaxf(tsc * sim + bias[0], -50.0f), 50.0f);
    const float zl = (m == c) ? logit : -logit;
    // stable log_sigmoid(zl) = min(zl,0) - log1p(exp(-|zl|))
    const float lsig = fminf(zl, 0.0f) - log1pf(expf(-fabsf(zl)));
    float v = -lsig;

#pragma unroll
    for (int o = 16; o > 0; o >>= 1) v += __shfl_xor_sync(0xffffffffu, v, o);
    __shared__ float sh[32];
    if ((t & 31) == 0) sh[t >> 5] = v;
    __syncthreads();
    if (t < 32) {
        float x = sh[t];
#pragma unroll
        for (int o = 16; o > 0; o >>= 1) x += __shfl_xor_sync(0xffffffffu, x, o);
        if (t == 0) out[0] = x * (1.0f / (Bn * Bn));
    }
}

// ---------------------------------------------------------------------------
// Launch: identify inputs by element count (robust to metadata ordering;
// the two size-1 scalars appear scale-before-bias in both orderings).
// All launches on the capture stream; graph-capturable (no syncs/allocs).
// ---------------------------------------------------------------------------
extern "C" void kernel_launch(void* const* d_in, const int* in_sizes, int n_in,
                              void* d_out, int out_size) {
    const float* img = nullptr;
    const float* con = nullptr;
    const int* lens = nullptr;
    const float* scale = nullptr;
    const float* bias = nullptr;
    for (int i = 0; i < n_in; i++) {
        const long s = in_sizes[i];
        if (s == (long)Bn * Np * Dd) img = (const float*)d_in[i];
        else if (s == (long)Bn * Wc * Dd) con = (const float*)d_in[i];
        else if (s == Bn) lens = (const int*)d_in[i];
        else if (s == 1) { if (!scale) scale = (const float*)d_in[i]; else bias = (const float*)d_in[i]; }
    }

    norm_kernel<<<Bn * Np, 64>>>(img, 0);
    norm_kernel<<<Bn * Wc, 64>>>(con, 1);
    dim3 grid(Bn, Bn);
    main_kernel<<<grid, 128>>>();
    finish_kernel<<<1, 1024>>>(lens, scale, bias, (float*)d_out);
}